// round 9
// baseline (speedup 1.0000x reference)
#include <cuda_runtime.h>
#include <cstdint>

#define C_IN   128
#define C_OUT  256
#define HH     56
#define WW     56
#define HW     3136
#define NPIX   100352
#define KTOT   1152          // 9 taps * 128 cin (tap-major k)
#define BM     128
#define BN     128
#define BK     16
#define KTILES 72
#define NPAIRS 36
#define TPB    256
#define STAGES 8

// smem: B only. [pixel(128)][16 words] (64B/pixel)
#define STG_WORDS   2048
#define SMEM_BYTES  (STAGES*STG_WORDS*4)     // 65536

// scratch: A in fragment-native tf32 layout, input in NHWC pi-permuted tf32
__device__ uint32_t g_wa[2*KTILES*512*4];            // 1.18 MB
__device__ uint32_t g_in2[(size_t)NPIX*C_IN];        // 51.4 MB

__device__ __forceinline__ uint32_t f2tf(float v) {
    uint32_t r;
    asm("cvt.rna.tf32.f32 %0, %1;" : "=r"(r) : "f"(v));
    return r;
}

// weights -> fragment-native tf32: word = (by*KT+kt)*2048 + ks*1024 + mf*128 + lane*4 + reg
__global__ void twa(const float* __restrict__ f) {
    int idx = blockIdx.x * 256 + threadIdx.x;
    if (idx >= 2*KTILES*512*4) return;
    int reg  = idx & 3;
    int lane = (idx >> 2) & 31;
    int mf   = (idx >> 7) & 7;
    int ks   = (idx >> 10) & 1;
    int r4   = idx >> 11;
    int kt   = r4 % KTILES;
    int by   = r4 / KTILES;
    int cout = by*128 + mf*16 + (lane >> 2) + 8*(reg & 1);
    int k    = kt*16 + ks*8 + (lane & 3) + 4*(reg >> 1);
    int tap  = k >> 7, cin = k & 127;
    g_wa[idx] = f2tf(f[(cout*C_IN + cin)*9 + tap]);
}

// input NCHW -> NHWC tf32, cin pi-permuted within each 16-group:
// pos = (c&~15) + 4*(c&3) + 2*((c>>3)&1) + ((c>>2)&1)
__global__ void tin(const float* __restrict__ in) {
    __shared__ float t[32][33];
    const int hw0 = blockIdx.x * 32, c0 = blockIdx.y * 32, n = blockIdx.z;
    const int tx = threadIdx.x, ty = threadIdx.y;
    const float* p = in + ((size_t)n*C_IN + c0)*HW + hw0;
    #pragma unroll
    for (int i = 0; i < 4; ++i)
        t[ty + 8*i][tx] = p[(size_t)(ty + 8*i)*HW + tx];
    __syncthreads();
    const int posloc = (tx & 16) + 4*(tx & 3) + 2*((tx >> 3) & 1) + ((tx >> 2) & 1);
    #pragma unroll
    for (int i = 0; i < 4; ++i) {
        int pix = ty + 8*i;
        g_in2[((size_t)(n*HW + hw0 + pix))*C_IN + c0 + posloc] = f2tf(t[tx][pix]);
    }
}

__device__ __forceinline__ uint32_t s2u(const void* p) {
    uint32_t a;
    asm("{ .reg .u64 t; cvta.to.shared.u64 t, %1; cvt.u32.u64 %0, t; }" : "=r"(a) : "l"(p));
    return a;
}
__device__ __forceinline__ void cp16(uint32_t dst, const void* src, uint32_t sz) {
    asm volatile("cp.async.cg.shared.global [%0], [%1], 16, %2;"
                 :: "r"(dst), "l"(src), "r"(sz));
}
__device__ __forceinline__ void mma_tf32(float* d, const uint32_t* a,
                                         uint32_t b0, uint32_t b1) {
    asm volatile(
        "mma.sync.aligned.m16n8k8.row.col.f32.tf32.tf32.f32 "
        "{%0,%1,%2,%3}, {%4,%5,%6,%7}, {%8,%9}, {%0,%1,%2,%3};"
        : "+f"(d[0]), "+f"(d[1]), "+f"(d[2]), "+f"(d[3])
        : "r"(a[0]), "r"(a[1]), "r"(a[2]), "r"(a[3]), "r"(b0), "r"(b1));
}

__global__ __launch_bounds__(TPB, 2)
void conv_mma(const float* __restrict__ bias, float* __restrict__ out) {
    extern __shared__ uint32_t sm[];
    const uint32_t sb = s2u(sm);
    const int tid  = threadIdx.x;
    const int warp = tid >> 5;
    const int lane = tid & 31;
    const int bx   = blockIdx.x;   // pixel block (784)
    const int by   = blockIdx.y;   // cout block (2)

    // ---- B copy: thread = pixel p0, two 16B chunks ----
    const int p0  = tid >> 1;
    const int kq  = (tid & 1) * 2;      // chunk pair base
    const int pix = bx * BN + p0;
    const int n   = pix / HW;
    const int hw  = pix - n * HW;
    const int h   = hw / WW;
    const int w   = hw - h * WW;
    const uint32_t bdst = (p0 * 16 + kq * 4) * 4;

    // ---- consumer: 8 warps, 4m x 2n, warp tile 32x64 ----
    const int wm = warp >> 1, wn = warp & 1;
    const uint32_t* a_gm = g_wa + (size_t)by * (KTILES * 2048) + (wm * 2) * 128 + lane * 4;

    float acc[2][8][4];
    #pragma unroll
    for (int i = 0; i < 2; ++i)
        #pragma unroll
        for (int j = 0; j < 8; ++j)
            #pragma unroll
            for (int q = 0; q < 4; ++q) acc[i][j][q] = 0.f;

    auto issue_copy = [&](int kt, int stg) {
        const uint32_t s0 = sb + stg * (STG_WORDS * 4);
        const int tap = kt >> 3;
        const int t3  = tap / 3;
        const int dh  = t3 - 1, dw = tap - t3 * 3 - 1;
        const bool v = ((unsigned)(h + dh) < HH) && ((unsigned)(w + dw) < WW);
        const uint32_t sz = v ? 16u : 0u;
        const int coff = (kt & 7) * 16 + kq * 4;
        const uint32_t* src = g_in2 + (size_t)(pix + dh * WW + dw) * C_IN + coff;
        cp16(s0 + bdst,      src,     sz);
        cp16(s0 + bdst + 16, src + 4, sz);
    };

    // prologue: 3 pairs (6 tiles), one commit group per pair
    #pragma unroll
    for (int pr = 0; pr < 3; ++pr) {
        issue_copy(2 * pr,     2 * pr);
        issue_copy(2 * pr + 1, 2 * pr + 1);
        asm volatile("cp.async.commit_group;" ::: "memory");
    }

    // prefetch A fragments for tile 0
    uint4 aN[2][2];   // [i][ks]
    #pragma unroll
    for (int i = 0; i < 2; ++i)
        #pragma unroll
        for (int ks = 0; ks < 2; ++ks)
            aN[i][ks] = *reinterpret_cast<const uint4*>(a_gm + ks * 1024 + i * 128);

    const int b_off = (wn * 64 + (lane >> 2)) * 16 + (lane & 3) * 4;

    int stg = 0;
    for (int t = 0; t < NPAIRS; ++t) {
        asm volatile("cp.async.wait_group 2;" ::: "memory");
        __syncthreads();

        #pragma unroll
        for (int half = 0; half < 2; ++half) {
            const int kt = 2 * t + half;
            uint32_t aw[2][2][4];
            #pragma unroll
            for (int i = 0; i < 2; ++i)
                #pragma unroll
                for (int ks = 0; ks < 2; ++ks) {
                    aw[i][ks][0] = aN[i][ks].x; aw[i][ks][1] = aN[i][ks].y;
                    aw[i][ks][2] = aN[i][ks].z; aw[i][ks][3] = aN[i][ks].w;
                }
            if (kt + 1 < KTILES) {
                const uint32_t* ap = a_gm + (size_t)(kt + 1) * 2048;
                #pragma unroll
                for (int i = 0; i < 2; ++i)
                    #pragma unroll
                    for (int ks = 0; ks < 2; ++ks)
                        aN[i][ks] = *reinterpret_cast<const uint4*>(ap + ks * 1024 + i * 128);
            }

            const uint32_t* s = sm + ((stg + half) & 7) * STG_WORDS;
            #pragma unroll
            for (int j = 0; j < 8; ++j) {
                uint4 bv = *reinterpret_cast<const uint4*>(s + b_off + j * 128);
                mma_tf32(acc[0][j], aw[0][0], bv.x, bv.y);
                mma_tf32(acc[1][j], aw[1][0], bv.x, bv.y);
                mma_tf32(acc[0][j], aw[0][1], bv.z, bv.w);
                mma_tf32(acc[1][j], aw[1][1], bv.z, bv.w);
            }
        }

        if (t + 3 < NPAIRS) {
            issue_copy(2 * t + 6, (stg + 6) & 7);
            issue_copy(2 * t + 7, (stg + 7) & 7);
        }
        asm volatile("cp.async.commit_group;" ::: "memory");
        stg = (stg + 2) & 7;
    }

    // ---- epilogue: bias + float2 stores ----
    const int eg = lane >> 2, et = lane & 3;
    #pragma unroll
    for (int i = 0; i < 2; ++i) {
        const int cout0 = by * BM + wm * 32 + i * 16 + eg;
        const float bz0 = bias[cout0];
        const float bz1 = bias[cout0 + 8];
        #pragma unroll
        for (int j = 0; j < 8; ++j) {
            const int pj  = bx * BN + wn * 64 + j * 8;       // 8-aligned, HW%8==0
            const int n2  = pj / HW;
            const int hw2 = pj - n2 * HW + et * 2;
            float2 v0 = make_float2(acc[i][j][0] + bz0, acc[i][j][1] + bz0);
            float2 v1 = make_float2(acc[i][j][2] + bz1, acc[i][j][3] + bz1);
            *reinterpret_cast<float2*>(out + ((size_t)(n2 * C_OUT + cout0))     * HW + hw2) = v0;
            *reinterpret_cast<float2*>(out + ((size_t)(n2 * C_OUT + cout0 + 8)) * HW + hw2) = v1;
        }
    }
}

extern "C" void kernel_launch(void* const* d_in, const int* in_sizes, int n_in,
                              void* d_out, int out_size) {
    const float* in   = (const float*)d_in[0];
    const float* fl   = (const float*)d_in[1];
    const float* bias = (const float*)d_in[2];
    float* out        = (float*)d_out;

    cudaFuncSetAttribute(conv_mma, cudaFuncAttributeMaxDynamicSharedMemorySize, SMEM_BYTES);

    twa<<<(2*KTILES*512*4 + 255) / 256, 256>>>(fl);
    dim3 tg(HW / 32, C_IN / 32, 32);
    tin<<<tg, dim3(32, 8)>>>(in);
    dim3 grid(NPIX / BN, C_OUT / BM);
    conv_mma<<<grid, TPB, SMEM_BYTES>>>(bias, out);
}

// round 10
// speedup vs baseline: 1.0927x; 1.0927x over previous
#include <cuda_runtime.h>
#include <cstdint>

#define C_IN   128
#define C_OUT  256
#define HH     56
#define WW     56
#define HW     3136
#define NPIX   100352
#define KTOT   1152          // 9 taps * 128 cin (tap-major k)
#define BM     128
#define BN     128
#define BK     16
#define KTILES 72
#define TPB    256
#define STAGES 8

// smem: B only. [pixel(128)][16 words] (64B/pixel)
#define STG_WORDS   2048
#define SMEM_BYTES  (STAGES*STG_WORDS*4)     // 65536

#define TWA_BLOCKS  1152                      // 2*KTILES*512*4 / 256
#define TIN_BLOCKS  (98*4*32)                 // (HW/32)*(C_IN/32)*N
#define PREP_BLOCKS (TWA_BLOCKS + TIN_BLOCKS)

// scratch: A in fragment-native tf32 layout, input in NHWC pi-permuted tf32
__device__ uint32_t g_wa[2*KTILES*512*4];            // 1.18 MB
__device__ uint32_t g_in2[(size_t)NPIX*C_IN];        // 51.4 MB

__device__ __forceinline__ uint32_t f2tf(float v) {
    uint32_t r;
    asm("cvt.rna.tf32.f32 %0, %1;" : "=r"(r) : "f"(v));
    return r;
}

// merged prepass:
//  blocks [0, TWA_BLOCKS): weights -> fragment-native tf32
//  blocks [TWA_BLOCKS, ..): input NCHW -> NHWC tf32, cin pi-permuted per 16-group
__global__ void prep(const float* __restrict__ f, const float* __restrict__ in) {
    __shared__ float t[32][33];
    if (blockIdx.x < TWA_BLOCKS) {
        int idx = blockIdx.x * 256 + threadIdx.x;
        int reg  = idx & 3;
        int lane = (idx >> 2) & 31;
        int mf   = (idx >> 7) & 7;
        int ks   = (idx >> 10) & 1;
        int r4   = idx >> 11;
        int kt   = r4 % KTILES;
        int by   = r4 / KTILES;
        int cout = by*128 + mf*16 + (lane >> 2) + 8*(reg & 1);
        int k    = kt*16 + ks*8 + (lane & 3) + 4*(reg >> 1);
        int tap  = k >> 7, cin = k & 127;
        g_wa[idx] = f2tf(f[(cout*C_IN + cin)*9 + tap]);
    } else {
        int bid = blockIdx.x - TWA_BLOCKS;
        const int hwb = bid % 98;            // hw block
        const int cb  = (bid / 98) % 4;      // channel block
        const int n   = bid / (98 * 4);
        const int hw0 = hwb * 32, c0 = cb * 32;
        const int tx = threadIdx.x & 31, ty = threadIdx.x >> 5;
        const float* p = in + ((size_t)n*C_IN + c0)*HW + hw0;
        #pragma unroll
        for (int i = 0; i < 4; ++i)
            t[ty + 8*i][tx] = p[(size_t)(ty + 8*i)*HW + tx];
        __syncthreads();
        const int posloc = (tx & 16) + 4*(tx & 3) + 2*((tx >> 3) & 1) + ((tx >> 2) & 1);
        #pragma unroll
        for (int i = 0; i < 4; ++i) {
            int pix = ty + 8*i;
            g_in2[((size_t)(n*HW + hw0 + pix))*C_IN + c0 + posloc] = f2tf(t[tx][pix]);
        }
    }
}

__device__ __forceinline__ uint32_t s2u(const void* p) {
    uint32_t a;
    asm("{ .reg .u64 t; cvta.to.shared.u64 t, %1; cvt.u32.u64 %0, t; }" : "=r"(a) : "l"(p));
    return a;
}
__device__ __forceinline__ void cp16(uint32_t dst, const void* src, uint32_t sz) {
    asm volatile("cp.async.cg.shared.global [%0], [%1], 16, %2;"
                 :: "r"(dst), "l"(src), "r"(sz));
}
__device__ __forceinline__ void mma_tf32(float* d, const uint32_t* a,
                                         uint32_t b0, uint32_t b1) {
    asm volatile(
        "mma.sync.aligned.m16n8k8.row.col.f32.tf32.tf32.f32 "
        "{%0,%1,%2,%3}, {%4,%5,%6,%7}, {%8,%9}, {%0,%1,%2,%3};"
        : "+f"(d[0]), "+f"(d[1]), "+f"(d[2]), "+f"(d[3])
        : "r"(a[0]), "r"(a[1]), "r"(a[2]), "r"(a[3]), "r"(b0), "r"(b1));
}

__global__ __launch_bounds__(TPB, 2)
void conv_mma(const float* __restrict__ bias, float* __restrict__ out) {
    extern __shared__ uint32_t sm[];
    const uint32_t sb = s2u(sm);
    const int tid  = threadIdx.x;
    const int warp = tid >> 5;
    const int lane = tid & 31;
    const int bx   = blockIdx.x;   // pixel block (784)
    const int by   = blockIdx.y;   // cout block (2)

    // ---- B copy: thread = pixel p0, two 16B chunks ----
    const int p0  = tid >> 1;
    const int kq  = (tid & 1) * 2;      // chunk pair base
    const int pix = bx * BN + p0;
    const int n   = pix / HW;
    const int hw  = pix - n * HW;
    const int h   = hw / WW;
    const int w   = hw - h * WW;
    const uint32_t bdst = (p0 * 16 + kq * 4) * 4;

    // ---- consumer: 8 warps, 4m x 2n, warp tile 32x64 ----
    const int wm = warp >> 1, wn = warp & 1;
    const uint32_t* a_gm = g_wa + (size_t)by * (KTILES * 2048) + (wm * 2) * 128 + lane * 4;

    float acc[2][8][4];
    #pragma unroll
    for (int i = 0; i < 2; ++i)
        #pragma unroll
        for (int j = 0; j < 8; ++j)
            #pragma unroll
            for (int q = 0; q < 4; ++q) acc[i][j][q] = 0.f;

    auto issue_copy = [&](int kt, int stg) {
        const uint32_t s0 = sb + stg * (STG_WORDS * 4);
        const int tap = kt >> 3;
        const int t3  = tap / 3;
        const int dh  = t3 - 1, dw = tap - t3 * 3 - 1;
        const bool v = ((unsigned)(h + dh) < HH) && ((unsigned)(w + dw) < WW);
        const uint32_t sz = v ? 16u : 0u;
        const int coff = (kt & 7) * 16 + kq * 4;
        const uint32_t* src = g_in2 + (size_t)(pix + dh * WW + dw) * C_IN + coff;
        cp16(s0 + bdst,      src,     sz);
        cp16(s0 + bdst + 16, src + 4, sz);
    };

    #pragma unroll
    for (int s = 0; s < STAGES - 1; ++s) {
        issue_copy(s, s);
        asm volatile("cp.async.commit_group;" ::: "memory");
    }

    // prefetch A fragments for tile 0
    uint4 aN[2][2];   // [i][ks]
    #pragma unroll
    for (int i = 0; i < 2; ++i)
        #pragma unroll
        for (int ks = 0; ks < 2; ++ks)
            aN[i][ks] = *reinterpret_cast<const uint4*>(a_gm + ks * 1024 + i * 128);

    const int b_off = (wn * 64 + (lane >> 2)) * 16 + (lane & 3) * 4;

    int stg = 0;
    for (int kt = 0; kt < KTILES; ++kt) {
        asm volatile("cp.async.wait_group 6;" ::: "memory");
        __syncthreads();

        uint32_t aw[2][2][4];
        #pragma unroll
        for (int i = 0; i < 2; ++i)
            #pragma unroll
            for (int ks = 0; ks < 2; ++ks) {
                aw[i][ks][0] = aN[i][ks].x; aw[i][ks][1] = aN[i][ks].y;
                aw[i][ks][2] = aN[i][ks].z; aw[i][ks][3] = aN[i][ks].w;
            }
        if (kt + 1 < KTILES) {
            const uint32_t* ap = a_gm + (size_t)(kt + 1) * 2048;
            #pragma unroll
            for (int i = 0; i < 2; ++i)
                #pragma unroll
                for (int ks = 0; ks < 2; ++ks)
                    aN[i][ks] = *reinterpret_cast<const uint4*>(ap + ks * 1024 + i * 128);
        }

        const uint32_t* s = sm + stg * STG_WORDS;
        #pragma unroll
        for (int j = 0; j < 8; ++j) {
            uint4 bv = *reinterpret_cast<const uint4*>(s + b_off + j * 128);
            mma_tf32(acc[0][j], aw[0][0], bv.x, bv.y);
            mma_tf32(acc[1][j], aw[1][0], bv.x, bv.y);
            mma_tf32(acc[0][j], aw[0][1], bv.z, bv.w);
            mma_tf32(acc[1][j], aw[1][1], bv.z, bv.w);
        }

        if (kt + STAGES - 1 < KTILES) {
            int ns = stg + STAGES - 1;
            if (ns >= STAGES) ns -= STAGES;
            issue_copy(kt + STAGES - 1, ns);
        }
        asm volatile("cp.async.commit_group;" ::: "memory");
        if (++stg == STAGES) stg = 0;
    }

    // ---- epilogue: bias + float2 stores ----
    const int eg = lane >> 2, et = lane & 3;
    #pragma unroll
    for (int i = 0; i < 2; ++i) {
        const int cout0 = by * BM + wm * 32 + i * 16 + eg;
        const float bz0 = bias[cout0];
        const float bz1 = bias[cout0 + 8];
        #pragma unroll
        for (int j = 0; j < 8; ++j) {
            const int pj  = bx * BN + wn * 64 + j * 8;       // 8-aligned, HW%8==0
            const int n2  = pj / HW;
            const int hw2 = pj - n2 * HW + et * 2;
            float2 v0 = make_float2(acc[i][j][0] + bz0, acc[i][j][1] + bz0);
            float2 v1 = make_float2(acc[i][j][2] + bz1, acc[i][j][3] + bz1);
            *reinterpret_cast<float2*>(out + ((size_t)(n2 * C_OUT + cout0))     * HW + hw2) = v0;
            *reinterpret_cast<float2*>(out + ((size_t)(n2 * C_OUT + cout0 + 8)) * HW + hw2) = v1;
        }
    }
}

extern "C" void kernel_launch(void* const* d_in, const int* in_sizes, int n_in,
                              void* d_out, int out_size) {
    const float* in   = (const float*)d_in[0];
    const float* fl   = (const float*)d_in[1];
    const float* bias = (const float*)d_in[2];
    float* out        = (float*)d_out;

    cudaFuncSetAttribute(conv_mma, cudaFuncAttributeMaxDynamicSharedMemorySize, SMEM_BYTES);

    prep<<<PREP_BLOCKS, 256>>>(fl, in);
    dim3 grid(NPIX / BN, C_OUT / BM);
    conv_mma<<<grid, TPB, SMEM_BYTES>>>(bias, out);
}

// round 11
// speedup vs baseline: 1.7375x; 1.5902x over previous
#include <cuda_runtime.h>
#include <cuda_fp16.h>
#include <cstdint>

#define C_IN   128
#define C_OUT  256
#define HH     56
#define WW     56
#define HW     3136
#define NPIX   100352
#define KTOT   1152          // 9 taps * 128 cin (tap-major k)
#define BM     128
#define BN     128
#define BK     16
#define KTILES 72
#define TPB    256
#define STAGES 8

// smem: B only. [pixel(128)][8 words] (32B/pixel, fp16)
#define STG_WORDS   1024
#define SMEM_BYTES  (STAGES*STG_WORDS*4)     // 32768

#define TWA_WORDS   (2*KTILES*1024)          // 147456 (each word = 2 fp16)
#define TWA_BLOCKS  (TWA_WORDS/256)          // 576
#define TIN_BLOCKS  (98*4*32)
#define PREP_BLOCKS (TWA_BLOCKS + TIN_BLOCKS)

// scratch: A fragment-native fp16 (packed pairs), input NHWC fp16 pair-permuted
__device__ uint32_t g_wa[TWA_WORDS];                 // 0.59 MB
__device__ __half   g_in2h[(size_t)NPIX*C_IN];       // 25.7 MB

// merged prepass
__global__ void prep(const float* __restrict__ f, const float* __restrict__ in) {
    __shared__ float t[32][33];
    if (blockIdx.x < TWA_BLOCKS) {
        // A: word = (by*KT+kt)*1024 + mf*128 + lane*4 + reg
        // reg r: row = mf*16 + (lane>>2) + 8*(r&1); k = kt*16 + (lane&3)*2 + 8*(r>>1) + {0,1}
        int idx  = blockIdx.x * 256 + threadIdx.x;
        int reg  = idx & 3;
        int lane = (idx >> 2) & 31;
        int mf   = (idx >> 7) & 7;
        int r10  = idx >> 10;
        int kt   = r10 % KTILES;
        int by   = r10 / KTILES;
        int cout = by*128 + mf*16 + (lane >> 2) + 8*(reg & 1);
        int k0   = kt*16 + (lane & 3)*2 + 8*(reg >> 1);
        int tap  = k0 >> 7, cin = k0 & 127;
        float lo = f[(cout*C_IN + cin)*9 + tap];
        float hi = f[(cout*C_IN + cin + 1)*9 + tap];
        __half2 h = __floats2half2_rn(lo, hi);
        g_wa[idx] = *reinterpret_cast<uint32_t*>(&h);
    } else {
        // B: NCHW -> per-pixel [128 fp16], per-16-group pair permutation:
        // pos(k) = 4*((k&7)>>1) + 2*((k>>3)&1) + (k&1)
        int bid = blockIdx.x - TWA_BLOCKS;
        const int hwb = bid % 98;
        const int cb  = (bid / 98) % 4;
        const int n   = bid / (98 * 4);
        const int hw0 = hwb * 32, c0 = cb * 32;
        const int tx = threadIdx.x & 31, ty = threadIdx.x >> 5;
        const float* p = in + ((size_t)n*C_IN + c0)*HW + hw0;
        #pragma unroll
        for (int i = 0; i < 4; ++i)
            t[ty + 8*i][tx] = p[(size_t)(ty + 8*i)*HW + tx];
        __syncthreads();
        const int k = tx & 15;
        const int posloc = (tx & 16) + 4*((k & 7) >> 1) + 2*((k >> 3) & 1) + (k & 1);
        #pragma unroll
        for (int i = 0; i < 4; ++i) {
            int pix = ty + 8*i;
            g_in2h[((size_t)(n*HW + hw0 + pix))*C_IN + c0 + posloc] =
                __float2half_rn(t[tx][pix]);
        }
    }
}

__device__ __forceinline__ uint32_t s2u(const void* p) {
    uint32_t a;
    asm("{ .reg .u64 t; cvta.to.shared.u64 t, %1; cvt.u32.u64 %0, t; }" : "=r"(a) : "l"(p));
    return a;
}
__device__ __forceinline__ void cp16(uint32_t dst, const void* src, uint32_t sz) {
    asm volatile("cp.async.cg.shared.global [%0], [%1], 16, %2;"
                 :: "r"(dst), "l"(src), "r"(sz));
}
__device__ __forceinline__ void mma16816(float* d, const uint32_t* a,
                                         uint32_t b0, uint32_t b1) {
    asm volatile(
        "mma.sync.aligned.m16n8k16.row.col.f32.f16.f16.f32 "
        "{%0,%1,%2,%3}, {%4,%5,%6,%7}, {%8,%9}, {%0,%1,%2,%3};"
        : "+f"(d[0]), "+f"(d[1]), "+f"(d[2]), "+f"(d[3])
        : "r"(a[0]), "r"(a[1]), "r"(a[2]), "r"(a[3]), "r"(b0), "r"(b1));
}

__global__ __launch_bounds__(TPB, 2)
void conv_mma(const float* __restrict__ bias, float* __restrict__ out) {
    extern __shared__ uint32_t sm[];
    const uint32_t sb = s2u(sm);
    const int tid  = threadIdx.x;
    const int warp = tid >> 5;
    const int lane = tid & 31;
    const int bx   = blockIdx.x;   // pixel block (784)
    const int by   = blockIdx.y;   // cout block (2)

    // ---- B copy: thread = (pixel p0, 16B chunk kq) ----
    const int p0  = tid >> 1;
    const int kq  = tid & 1;
    const int pix = bx * BN + p0;
    const int n   = pix / HW;
    const int hw  = pix - n * HW;
    const int h   = hw / WW;
    const int w   = hw - h * WW;
    const uint32_t bdst = p0 * 32 + kq * 16;

    // ---- consumer: 8 warps, 4m x 2n, warp tile 32x64 ----
    const int wm = warp >> 1, wn = warp & 1;
    const uint32_t* a_gm = g_wa + (size_t)by * (KTILES * 1024) + (wm * 2) * 128 + lane * 4;

    float acc[2][8][4];
    #pragma unroll
    for (int i = 0; i < 2; ++i)
        #pragma unroll
        for (int j = 0; j < 8; ++j)
            #pragma unroll
            for (int q = 0; q < 4; ++q) acc[i][j][q] = 0.f;

    auto issue_copy = [&](int kt, int stg) {
        const uint32_t s0 = sb + stg * (STG_WORDS * 4);
        const int tap = kt >> 3;
        const int t3  = tap / 3;
        const int dh  = t3 - 1, dw = tap - t3 * 3 - 1;
        const bool v = ((unsigned)(h + dh) < HH) && ((unsigned)(w + dw) < WW);
        const int coff = (kt & 7) * 16 + kq * 8;
        const __half* src = g_in2h + (size_t)(pix + dh * WW + dw) * C_IN + coff;
        cp16(s0 + bdst, src, v ? 16u : 0u);
    };

    #pragma unroll
    for (int s = 0; s < STAGES - 1; ++s) {
        issue_copy(s, s);
        asm volatile("cp.async.commit_group;" ::: "memory");
    }

    // prefetch A fragments for tile 0 (one uint4 per m-frag = full k16)
    uint4 aN[2];
    #pragma unroll
    for (int i = 0; i < 2; ++i)
        aN[i] = *reinterpret_cast<const uint4*>(a_gm + i * 128);

    const int b_off = (wn * 64 + (lane >> 2)) * 8 + (lane & 3) * 2;

    int stg = 0;
    for (int kt = 0; kt < KTILES; ++kt) {
        asm volatile("cp.async.wait_group 6;" ::: "memory");
        __syncthreads();

        uint32_t aw[2][4];
        #pragma unroll
        for (int i = 0; i < 2; ++i) {
            aw[i][0] = aN[i].x; aw[i][1] = aN[i].y;
            aw[i][2] = aN[i].z; aw[i][3] = aN[i].w;
        }
        if (kt + 1 < KTILES) {
            const uint32_t* ap = a_gm + (size_t)(kt + 1) * 1024;
            #pragma unroll
            for (int i = 0; i < 2; ++i)
                aN[i] = *reinterpret_cast<const uint4*>(ap + i * 128);
        }

        const uint32_t* s = sm + stg * STG_WORDS;
        #pragma unroll
        for (int j = 0; j < 8; ++j) {
            uint2 bv = *reinterpret_cast<const uint2*>(s + b_off + j * 64);
            mma16816(acc[0][j], aw[0], bv.x, bv.y);
            mma16816(acc[1][j], aw[1], bv.x, bv.y);
        }

        if (kt + STAGES - 1 < KTILES) {
            int ns = stg + STAGES - 1;
            if (ns >= STAGES) ns -= STAGES;
            issue_copy(kt + STAGES - 1, ns);
        }
        asm volatile("cp.async.commit_group;" ::: "memory");
        if (++stg == STAGES) stg = 0;
    }

    // ---- epilogue: bias + float2 stores ----
    const int eg = lane >> 2, et = lane & 3;
    #pragma unroll
    for (int i = 0; i < 2; ++i) {
        const int cout0 = by * BM + wm * 32 + i * 16 + eg;
        const float bz0 = bias[cout0];
        const float bz1 = bias[cout0 + 8];
        #pragma unroll
        for (int j = 0; j < 8; ++j) {
            const int pj  = bx * BN + wn * 64 + j * 8;       // 8-aligned, HW%8==0
            const int n2  = pj / HW;
            const int hw2 = pj - n2 * HW + et * 2;
            float2 v0 = make_float2(acc[i][j][0] + bz0, acc[i][j][1] + bz0);
            float2 v1 = make_float2(acc[i][j][2] + bz1, acc[i][j][3] + bz1);
            *reinterpret_cast<float2*>(out + ((size_t)(n2 * C_OUT + cout0))     * HW + hw2) = v0;
            *reinterpret_cast<float2*>(out + ((size_t)(n2 * C_OUT + cout0 + 8)) * HW + hw2) = v1;
        }
    }
}

extern "C" void kernel_launch(void* const* d_in, const int* in_sizes, int n_in,
                              void* d_out, int out_size) {
    const float* in   = (const float*)d_in[0];
    const float* fl   = (const float*)d_in[1];
    const float* bias = (const float*)d_in[2];
    float* out        = (float*)d_out;

    cudaFuncSetAttribute(conv_mma, cudaFuncAttributeMaxDynamicSharedMemorySize, SMEM_BYTES);

    prep<<<PREP_BLOCKS, 256>>>(fl, in);
    dim3 grid(NPIX / BN, C_OUT / BM);
    conv_mma<<<grid, TPB, SMEM_BYTES>>>(bias, out);
}